// round 4
// baseline (speedup 1.0000x reference)
#include <cuda_runtime.h>

// 32 images * 64 tiles = 2048 tiles; each tile split into 4 quarter-tiles
// (32 rows x 128 cols). One CTA per quarter-tile -> 8192 CTAs.
#define NUM_TILES    2048
#define NUM_QUARTERS 8192
__device__ float g_partials[NUM_QUARTERS];   // [tile*4 + quarter]
__device__ unsigned int g_done_count = 0;

__device__ __forceinline__ float block_reduce(float acc, float* warp_sums)
{
    #pragma unroll
    for (int off = 16; off > 0; off >>= 1)
        acc += __shfl_xor_sync(0xFFFFFFFFu, acc, off);

    int wid = threadIdx.x >> 5;
    int lid = threadIdx.x & 31;
    if (lid == 0) warp_sums[wid] = acc;
    __syncthreads();

    float v = 0.0f;
    if (wid == 0) {
        v = (lid < 8) ? warp_sums[lid] : 0.0f;
        #pragma unroll
        for (int off = 4; off > 0; off >>= 1)
            v += __shfl_xor_sync(0xFFFFFFFFu, v, off);
    }
    return v;   // lane 0 of warp 0 authoritative
}

__global__ __launch_bounds__(256) void lthu_kernel(
    const float* __restrict__ fake, const float* __restrict__ real,
    float* __restrict__ out)
{
    __shared__ float warp_sums[8];
    __shared__ bool is_last;

    const int blk  = blockIdx.x;          // 0..8191
    const int tile = blk >> 2;            // 0..2047
    const int q    = blk & 3;             // quarter 0..3 (rows q*32 .. q*32+31)

    const int b   = tile >> 6;            // image (64 tiles per image)
    const int rem = tile & 63;
    const int by  = rem >> 3;
    const int bx  = rem & 7;
    const long base = (long)b * (1024 * 1024)
                    + (long)(by * 128 + q * 32) * 1024
                    + (long)bx * 128;

    const float4* f4 = (const float4*)(fake + base);
    const float4* r4 = (const float4*)(real + base);
    // quarter-tile: 32 rows x 32 float4/row; row stride in float4 = 256

    float acc = 0.0f;
    #pragma unroll
    for (int it = 0; it < 4; ++it) {
        int i   = threadIdx.x + it * 256;  // 0..1023
        int row = i >> 5;
        int c4  = i & 31;
        float4 fv = f4[row * 256 + c4];
        float4 rv = r4[row * 256 + c4];
        acc += (fv.x - rv.x) + (fv.y - rv.y) + (fv.z - rv.z) + (fv.w - rv.w);
    }

    float qsum = block_reduce(acc, warp_sums);

    if (threadIdx.x == 0) {
        g_partials[blk] = qsum;            // signed; abs applied per full tile
        __threadfence();
        unsigned int prev = atomicAdd(&g_done_count, 1u);
        is_last = (prev == NUM_QUARTERS - 1);
    }
    __syncthreads();

    if (is_last) {
        // fixed-order deterministic reduce: per tile, sum 4 quarters then abs
        float s = 0.0f;
        #pragma unroll
        for (int it = 0; it < 8; ++it) {
            int t = threadIdx.x + it * 256;          // tile index 0..2047
            const float* p = &g_partials[t * 4];
            s += fabsf(p[0] + p[1] + p[2] + p[3]);
        }

        float total = block_reduce(s, warp_sums);
        if (threadIdx.x == 0) {
            out[0] = total * (1.0f / (16384.0f * 32.0f));
            g_done_count = 0;   // reset for next graph replay
        }
    }
}

extern "C" void kernel_launch(void* const* d_in, const int* in_sizes, int n_in,
                              void* d_out, int out_size)
{
    const float* fake = (const float*)d_in[0];
    const float* real = (const float*)d_in[1];
    float* out = (float*)d_out;

    lthu_kernel<<<NUM_QUARTERS, 256>>>(fake, real, out);
}

// round 5
// speedup vs baseline: 1.0942x; 1.0942x over previous
#include <cuda_runtime.h>

// 32 images * 64 tiles = 2048 tiles; each tile = 4 row-slices (32 rows x 128 cols)
// 8192 slices, one per warp. Grid = 1024 CTAs x 256 thr = 8192 warps, single wave.
#define NUM_TILES  2048
#define NUM_SLICES 8192
#define NUM_CTAS   1024
__device__ float g_partials[NUM_SLICES];   // signed slice sums, [tile*4 + q]
__device__ unsigned int g_done_count = 0;

__global__ void __launch_bounds__(256, 7) lthu_kernel(
    const float* __restrict__ fake, const float* __restrict__ real,
    float* __restrict__ out)
{
    __shared__ float warp_sums[8];
    __shared__ bool is_last;

    const int lane  = threadIdx.x & 31;
    const int wid   = threadIdx.x >> 5;
    const int slice = blockIdx.x * 8 + wid;   // 0..8191

    const int tile = slice >> 2;              // 0..2047
    const int q    = slice & 3;               // row group q*32 .. q*32+31
    const int b    = tile >> 6;               // image (64 tiles per image)
    const int rem  = tile & 63;
    const int by   = rem >> 3;
    const int bx   = rem & 7;
    const long base = (long)b * (1024 * 1024)
                    + (long)(by * 128 + q * 32) * 1024
                    + (long)bx * 128;

    const float4* f4 = (const float4*)(fake + base);
    const float4* r4 = (const float4*)(real + base);
    // slice: 32 rows x 32 float4/row; row stride in float4 units = 256

    // warp covers one row per iteration (32 lanes x float4 = 128 floats)
    float acc = 0.0f;
    #pragma unroll 16
    for (int r = 0; r < 32; ++r) {
        float4 fv = f4[r * 256 + lane];
        float4 rv = r4[r * 256 + lane];
        acc += (fv.x - rv.x) + (fv.y - rv.y) + (fv.z - rv.z) + (fv.w - rv.w);
    }

    // warp-local reduce — no CTA barrier, other warps keep streaming
    #pragma unroll
    for (int off = 16; off > 0; off >>= 1)
        acc += __shfl_xor_sync(0xFFFFFFFFu, acc, off);

    if (lane == 0)
        g_partials[slice] = acc;   // signed; abs applied per full tile later

    __syncthreads();               // single barrier, after all loads are done

    if (threadIdx.x == 0) {
        __threadfence();
        unsigned int prev = atomicAdd(&g_done_count, 1u);
        is_last = (prev == NUM_CTAS - 1);
    }
    __syncthreads();

    if (is_last) {
        // fixed-order deterministic reduce: per tile sum 4 slices, abs, sum
        float s = 0.0f;
        #pragma unroll
        for (int it = 0; it < 8; ++it) {
            int t = threadIdx.x + it * 256;        // tile 0..2047
            const float* p = &g_partials[t * 4];
            s += fabsf(p[0] + p[1] + p[2] + p[3]);
        }

        // block reduce of s
        #pragma unroll
        for (int off = 16; off > 0; off >>= 1)
            s += __shfl_xor_sync(0xFFFFFFFFu, s, off);
        if (lane == 0) warp_sums[wid] = s;
        __syncthreads();
        if (wid == 0) {
            float v = (lane < 8) ? warp_sums[lane] : 0.0f;
            #pragma unroll
            for (int off = 4; off > 0; off >>= 1)
                v += __shfl_xor_sync(0xFFFFFFFFu, v, off);
            if (lane == 0) {
                out[0] = v * (1.0f / (16384.0f * 32.0f));
                g_done_count = 0;   // reset for next graph replay
            }
        }
    }
}

extern "C" void kernel_launch(void* const* d_in, const int* in_sizes, int n_in,
                              void* d_out, int out_size)
{
    const float* fake = (const float*)d_in[0];
    const float* real = (const float*)d_in[1];
    float* out = (float*)d_out;

    lthu_kernel<<<NUM_CTAS, 256>>>(fake, real, out);
}